// round 14
// baseline (speedup 1.0000x reference)
#include <cuda_runtime.h>
#include <math.h>
#include <limits.h>
#include <stdint.h>

// Problem constants
#define TT   10000
#define BB   4096
#define CH   8              // t-rows per chunk
#define KGX  4              // lane groups (KGX*1024 == BB)
#define KGY  138            // chunk groups (covers ta <= 1104 in one shot)
#define NBLK (KGX * KGY)    // kill blocks; +1 scan block
#define NTHR 256
#define EPT  40             // scan: elements per thread (250 active threads)
#define LCAP 1024           // per-chunk candidate capacity

#define LOG_GAMMA_C ( 0.019802627296179713f)   // ln(1.02)
#define ALPHA_C     (-1.0050335853501451e-05f) // ln(0.99)/1000
#define INIT_LOGW_C (-1.3943265327605025f)     // ln(0.248)
#define INIT_LOGP_C (-6.907755278982137f)      // ln(0.001)
#define INV_TEMP_C  (0.001f)
#define EPSF        (1e-12f)

// Persistent device state. INVARIANT: all-zero at entry and exit (zero static
// init; last finishing block restores zeros) so graph replays are identical.
// g_tk encoding: v = max over kills of (TT - t); v==0 means never; t_kill = TT-v.
__device__ float2       g_row[TT];      // {thr, rm}: u2 filter threshold, r - eps
__device__ float        g_pref[TT + 1]; // exclusive prefix of W_t
__device__ int          g_tactive;
__device__ int          g_tk[BB];
__device__ unsigned int g_done;
__device__ int          g_ready;

// ---------------------------------------------------------------------------
// cp.async helpers (per-thread LDGSTS — measured 2x faster than bulk DMA here)
// ---------------------------------------------------------------------------
__device__ __forceinline__ void cp_async16(uint32_t saddr, const void* gaddr) {
    asm volatile("cp.async.cg.shared.global [%0], [%1], 16;\n"
                 :: "r"(saddr), "l"(gaddr) : "memory");
}
__device__ __forceinline__ void cp_async_wait_all() {
    asm volatile("cp.async.commit_group;\ncp.async.wait_group 0;\n" ::: "memory");
}
__device__ __forceinline__ int ld_cg(const int* p) {
    int v;
    asm volatile("ld.global.cg.b32 %0, [%1];" : "=r"(v) : "l"(p));
    return v;
}

// ---------------------------------------------------------------------------
// Block-wide exclusive scan, 8 warps (256 threads)
// ---------------------------------------------------------------------------
__device__ __forceinline__ float block_exscan8(float v, float* ws) {
    const int lane = threadIdx.x & 31;
    const int wid  = threadIdx.x >> 5;
    float s = v;
#pragma unroll
    for (int o = 1; o < 32; o <<= 1) {
        float n = __shfl_up_sync(0xffffffffu, s, o);
        if (lane >= o) s += n;
    }
    float exw = __shfl_up_sync(0xffffffffu, s, 1);
    if (lane == 0) exw = 0.0f;
    if (lane == 31) ws[wid] = s;
    __syncthreads();
    if (wid == 0) {
        float t = (lane < 8) ? ws[lane] : 0.0f;
#pragma unroll
        for (int o = 1; o < 8; o <<= 1) {
            float n = __shfl_up_sync(0xffffffffu, t, o);
            if (lane >= o) t += n;
        }
        float exb = __shfl_up_sync(0xffffffffu, t, 1);
        if (lane == 0) exb = 0.0f;
        if (lane < 8) ws[lane] = exb;
    }
    __syncthreads();
    return ws[wid] + exw;
}

// ---------------------------------------------------------------------------
// Single fused kernel.
//  block 0        : scan (per-t tables from acts), releases g_ready
//  blocks 1..NBLK : fire per-thread cp.async prefetch of their u2 chunk,
//                   poll g_ready (overlapped), two-phase kill search,
//                   ticketed final reduction + state reset
// ---------------------------------------------------------------------------
__global__ void __launch_bounds__(NTHR)
fused_kernel(const float* __restrict__ acts, const float* __restrict__ u1,
             const float* __restrict__ u2, float* __restrict__ out) {
    __shared__ __align__(16) char s_raw[40960];  // scan: f[10000] | kill: u2 32K + lists 8K
    __shared__ float2 s_row[CH];
    __shared__ float  s_ws[32];
    __shared__ int  s_cnt, sh_ta;
    __shared__ bool s_last;

    const int tid = threadIdx.x;
    const int bid = blockIdx.x;

    // ======================= SCAN BLOCK =======================
    if (bid == 0) {
        {   // stage f = exp(acts) into smem (coalesced float4)
            const float4* a4 = (const float4*)acts;
            float4* f4 = (float4*)s_raw;
            for (int i = tid; i < TT / 4; i += NTHR) {
                float4 a = a4[i];
                f4[i] = make_float4(__expf(a.x), __expf(a.y), __expf(a.z), __expf(a.w));
            }
        }
        __syncthreads();
        const float* s_f = (const float*)s_raw;
        const int  base = tid * EPT;
        const bool act  = (base < TT);

        float csum = 0.0f;
        if (act) {
#pragma unroll 4
            for (int i = 0; i < EPT; ++i)
                csum += LOG_GAMMA_C + __logf(1.0f - s_f[base + i]);
        }
        const float coff = block_exscan8(act ? csum : 0.0f, s_ws);
        const float lw0  = INIT_LOGW_C + coff;

        float dsum = 0.0f, wsum = 0.0f;
        if (act) {
            float elw = __expf(lw0), wv = __expf(lw0 * INV_TEMP_C), lwl = 0.0f;
#pragma unroll 4
            for (int i = 0; i < EPT; ++i) {
                float fv = s_f[base + i];
                float c  = LOG_GAMMA_C + __logf(1.0f - fv);
                dsum += ALPHA_C * fv * elw;
                elw  *= 1.02f * (1.0f - fv);
                lwl  += c;
                float x = lwl * INV_TEMP_C;
                wsum += wv * (1.0f + x * (1.0f + 0.5f * x));
            }
        }
        const float doff = block_exscan8(act ? dsum : 0.0f, s_ws);
        const float woff = block_exscan8(act ? wsum : 0.0f, s_ws);

        // emit tables.  e = exp(logp) <= 1e-3 always (logp only decreases), so
        // log1p(-e), e/(1-e), exp(-28r) are tiny-argument polynomials (err<=3e-8).
        int poss = -1;
        if (act) {
            float elw = __expf(lw0), wv = __expf(lw0 * INV_TEMP_C), lwl = 0.0f;
            float lp = INIT_LOGP_C + doff, pw = woff;
#pragma unroll 4
            for (int i = 0; i < EPT; ++i) {
                float fv = s_f[base + i];
                float c  = LOG_GAMMA_C + __logf(1.0f - fv);
                float dd = ALPHA_C * fv * elw;
                elw *= 1.02f * (1.0f - fv);
                lwl += c;
                float x = lwl * INV_TEMP_C;
                float ww = wv * (1.0f + x * (1.0f + 0.5f * x));
                g_pref[base + i] = pw;  pw += ww;
                float e = __expf(lp);
                float logit = lp + e * (1.0f + 0.5f * e);
                float r = e * (1.0f + e);
                // kill needs u2 + eps > exp(-27.631*r); 28 / -1e-5 = margins
                float xx = 28.0f * r;
                float thr = 1.0f - xx * (1.0f - 0.5f * xx * (1.0f - 0.33333334f * xx)) - 1e-5f;
                g_row[base + i] = make_float2(thr, r - EPSF);
                if (logit > -20.5f) poss = base + i;  // noise <= 19.95 always
                lp += dd;
            }
            if (base + EPT == TT) g_pref[TT] = pw;
        }

        if (tid == 0) sh_ta = 0;
        __syncthreads();
        if (poss >= 0) atomicMax(&sh_ta, poss + 1);
        __syncthreads();
        if (tid == 0) {
            g_tactive = sh_ta;
            __threadfence();
            atomicExch(&g_ready, 1);   // release tables to kill blocks
        }
        return;
    }

    // ======================= KILL BLOCKS =======================
    const int kid = bid - 1;
    const int kx  = kid & (KGX - 1);       // lane group: lanes [kx*1024, +1024)
    const int ky  = kid >> 2;              // chunk group
    const float4* __restrict__ u2v = (const float4*)u2;
    const uint32_t s_base = (uint32_t)__cvta_generic_to_shared(s_raw) + tid * 16u;
    float*    s_val = (float*)(s_raw + 32768);
    uint32_t* s_pk  = (uint32_t*)(s_raw + 36864);

    // fire the prefetch for chunk ky immediately (independent of scan results)
#pragma unroll
    for (int i = 0; i < CH; ++i) {
        int tt = min(ky * CH + i, TT - 1);
        cp_async16(s_base + i * (256 * 16), u2v + tt * (BB / 4) + kx * 256 + tid);
    }

    // poll for scan tables with plain cached loads (overlaps the DMA above)
    if (tid == 0) {
        while (ld_cg(&g_ready) == 0) __nanosleep(128);
    }
    __syncthreads();
    __threadfence();
    const int ta      = g_tactive;
    const int nchunks = (ta + CH - 1) / CH;

    for (int cy = ky; cy < nchunks; cy += KGY) {
        const int t0 = cy * CH;
        if (tid == 0) s_cnt = 0;
        if (tid < CH) s_row[tid] = g_row[min(t0 + tid, TT - 1)];
        if (cy != ky) {   // refill (only if ta > KGY*CH — statistically never)
            __syncthreads();
#pragma unroll
            for (int i = 0; i < CH; ++i) {
                int tt = min(t0 + i, TT - 1);
                cp_async16(s_base + i * (256 * 16), u2v + tt * (BB / 4) + kx * 256 + tid);
            }
        }
        cp_async_wait_all();     // waits this thread's own group; own slots only
        __syncthreads();         // s_row + s_cnt visibility

        const int rmax = min(CH, ta - t0);
        const float4* u2s = (const float4*)s_raw;
        // ---- Phase A: pure filter, append candidates (no global loads) ----
#pragma unroll
        for (int i = 0; i < CH; ++i) {
            if (i >= rmax) break;
            const float  thr = s_row[i].x;
            const float4 vv  = u2s[i * 256 + tid];
            const float  m   = fmaxf(fmaxf(vv.x, vv.y), fmaxf(vv.z, vv.w));
            if (m > thr) {
                const uint32_t pkb = ((uint32_t)i << 10) | ((uint32_t)tid << 2);
                float vs[4] = {vv.x, vv.y, vv.z, vv.w};
#pragma unroll
                for (int sub = 0; sub < 4; ++sub) {
                    if (vs[sub] > thr) {
                        int slot = atomicAdd(&s_cnt, 1);
                        if (slot < LCAP) {
                            s_val[slot] = vs[sub];
                            s_pk[slot]  = pkb | (uint32_t)sub;
                        } else {   // statistically-never fallback: direct eval
                            int gl = kx * 1024 + (int)(pkb & 1023u) + sub;
                            float L1 = __logf(u1[(t0 + i) * BB + gl] + EPSF);
                            float L2 = __logf(vs[sub] + EPSF);
                            if (L2 > s_row[i].y * L1) atomicMax(&g_tk[gl], TT - (t0 + i));
                        }
                    }
                }
            }
        }
        __syncthreads();

        // ---- Phase B: burst evaluation (all u1 loads in one round) ----
        // exact: sigmoid(logit+noise)>0.5 <=> L2/L1+eps < r <=> L2 > (r-eps)*L1
        const int n = min(s_cnt, LCAP);
        for (int j = tid; j < n; j += NTHR) {
            const uint32_t pk = s_pk[j];
            const int i  = (int)(pk >> 10);
            const int gl = kx * 1024 + (int)(pk & 1023u);
            const int t  = t0 + i;
            float L1 = __logf(u1[t * BB + gl] + EPSF);
            float L2 = __logf(s_val[j] + EPSF);
            if (L2 > s_row[i].y * L1) atomicMax(&g_tk[gl], TT - t);
        }
    }

    // ---- ticketed final reduction + state reset (keeps zero-invariant) ----
    __threadfence();
    if (tid == 0) s_last = (atomicAdd(&g_done, 1u) == NBLK - 1u);
    __syncthreads();
    if (!s_last) return;
    __threadfence();

    int kk[BB / NTHR];
#pragma unroll
    for (int it = 0; it < BB / NTHR; ++it) kk[it] = g_tk[tid + it * NTHR];
#pragma unroll
    for (int it = 0; it < BB / NTHR; ++it) g_tk[tid + it * NTHR] = 0;  // reset
    double s = 0.0;
#pragma unroll
    for (int it = 0; it < BB / NTHR; ++it) s += (double)g_pref[TT - kk[it]];

    double* sh = (double*)s_raw;
    sh[tid] = s;
    __syncthreads();
#pragma unroll
    for (int off = 128; off > 0; off >>= 1) {
        if (tid < off) sh[tid] += sh[tid + off];
        __syncthreads();
    }
    if (tid == 0) {
        out[0] = (float)(sh[0] / (double)BB);
        g_done  = 0u;
        g_ready = 0;
    }
}

// ---------------------------------------------------------------------------
extern "C" void kernel_launch(void* const* d_in, const int* in_sizes, int n_in,
                              void* d_out, int out_size) {
    const float* acts = (const float*)d_in[0];
    const float* u1   = (const float*)d_in[1];
    const float* u2   = (const float*)d_in[2];

    fused_kernel<<<NBLK + 1, NTHR>>>(acts, u1, u2, (float*)d_out);
}

// round 17
// speedup vs baseline: 1.1526x; 1.1526x over previous
#include <cuda_runtime.h>
#include <math.h>
#include <limits.h>
#include <stdint.h>

// Problem constants
#define TT   10000
#define BB   4096
#define NTH  1024
#define EPT  10             // scan: elements per thread
#define RPP  1280           // kill: rows per pass (>= ta ~1104, loop covers more)
#define NBLK 2560           // kill blocks: RPP rows * 16 warps/row / 8 warps/block
#define NTHR 256

#define LOG_GAMMA_C ( 0.019802627296179713f)   // ln(1.02)
#define ALPHA_C     (-1.0050335853501451e-05f) // ln(0.99)/1000
#define INIT_LOGW_C (-1.3943265327605025f)     // ln(0.248)
#define INIT_LOGP_C (-6.907755278982137f)      // ln(0.001)
#define INV_TEMP_C  (0.001f)
#define EPSF        (1e-12f)

// Scratch (no allocations allowed)
__device__ float2       g_row[TT];      // {thr, rm}: u2 filter threshold, r - eps
__device__ float        g_pref[TT + 1]; // exclusive prefix of W_t
__device__ int          g_tactive;
__device__ int          g_tkill[BB];    // per-lane first kill step (TT = never)
__device__ unsigned int g_done;

// ---------------------------------------------------------------------------
// Block-wide exclusive scan via warp shuffles (2 barriers), 1024 threads
// ---------------------------------------------------------------------------
__device__ __forceinline__ float block_exscan(float v) {
    __shared__ float ws[32];
    const int lane = threadIdx.x & 31;
    const int wid  = threadIdx.x >> 5;
    float s = v;
#pragma unroll
    for (int o = 1; o < 32; o <<= 1) {
        float n = __shfl_up_sync(0xffffffffu, s, o);
        if (lane >= o) s += n;
    }
    float exw = __shfl_up_sync(0xffffffffu, s, 1);
    if (lane == 0) exw = 0.0f;
    if (lane == 31) ws[wid] = s;
    __syncthreads();
    if (wid == 0) {
        float t = ws[lane];
#pragma unroll
        for (int o = 1; o < 32; o <<= 1) {
            float n = __shfl_up_sync(0xffffffffu, t, o);
            if (lane >= o) t += n;
        }
        float exb = __shfl_up_sync(0xffffffffu, t, 1);
        if (lane == 0) exb = 0.0f;
        ws[lane] = exb;
    }
    __syncthreads();
    return ws[wid] + exw;
}

// ---------------------------------------------------------------------------
// K1 (single block): everything that depends only on acts (unchanged from the
// best 31.2us config). e = exp(logp) <= 1e-3 always, so log1p(-e), e/(1-e),
// exp(-28r) collapse to tiny-argument polynomials (abs err <= 3e-8).
// ---------------------------------------------------------------------------
__global__ void __launch_bounds__(NTH) scan_kernel(const float* __restrict__ acts) {
    __shared__ float s_acts[TT];   // 40 KB, coalesced staging
    const int tid = threadIdx.x;

    {   // coalesced float4 burst load of acts
        const float4* a4 = (const float4*)acts;
        float4* s4 = (float4*)s_acts;
        for (int i = tid; i < TT / 4; i += NTH) s4[i] = a4[i];
    }
    // reset per-lane kill step + ticket early (independent stores)
    for (int b = tid; b < BB; b += NTH) g_tkill[b] = TT;
    if (tid == 0) g_done = 0u;
    __syncthreads();

    const int base = tid * EPT;
    const bool act = (base < TT);

    float f[EPT], c[EPT], d[EPT], w[EPT];
    float csum = 0.0f;
    if (act) {
#pragma unroll
        for (int i = 0; i < EPT; ++i) {
            float a = s_acts[base + i];
            f[i] = __expf(a);
            c[i] = LOG_GAMMA_C + __logf(1.0f - f[i]);
            csum += c[i];
        }
    }
    float coff = block_exscan(act ? csum : 0.0f);

    float dsum = 0.0f, wsum = 0.0f;
    if (act) {
        float lw0 = INIT_LOGW_C + coff;
        float elw = __expf(lw0);
        float wv  = __expf(lw0 * INV_TEMP_C);
        float lwl = 0.0f;
#pragma unroll
        for (int i = 0; i < EPT; ++i) {
            d[i] = ALPHA_C * f[i] * elw;        // uses OLD logw (matches ref)
            elw *= 1.02f * (1.0f - f[i]);       // exp(logw_{t+1})
            lwl += c[i];
            float x = lwl * INV_TEMP_C;         // |x| <= 2e-4
            w[i] = wv * (1.0f + x * (1.0f + 0.5f * x));
            dsum += d[i];
            wsum += w[i];
        }
    }
    float doff = block_exscan(act ? dsum : 0.0f);
    float woff = block_exscan(act ? wsum : 0.0f);

    int poss = -1;
    if (act) {
        float lp = INIT_LOGP_C + doff;
        float pw = woff;
#pragma unroll
        for (int i = 0; i < EPT; ++i) {
            g_pref[base + i] = pw;  pw += w[i];
            float e = __expf(lp);                       // e <= 1e-3
            float logit = lp + e * (1.0f + 0.5f * e);   // lp - log1p(-e)
            float r = e * (1.0f + e);                   // e/(1-e)
            // kill needs u2 + eps > exp(-27.631*r); 28 / -1e-5 = safety margin
            float x = 28.0f * r;                        // x <= 0.029
            float thr = 1.0f - x * (1.0f - 0.5f * x * (1.0f - 0.33333334f * x)) - 1e-5f;
            g_row[base + i] = make_float2(thr, r - EPSF);
            // noise <= 19.95 always, so logit < -20.5 => kill impossible
            if (logit > -20.5f) poss = base + i;
            lp += d[i];
        }
        if (base + EPT == TT) g_pref[TT] = pw;
    }

    __shared__ int sh_ta;
    if (tid == 0) sh_ta = 0;
    __syncthreads();
    if (poss >= 0) atomicMax(&sh_ta, poss + 1);
    __syncthreads();
    if (tid == 0) g_tactive = sh_ta;
}

// ---------------------------------------------------------------------------
// K2: flat kill search — warp = (row, 64-quad segment), thread = 2 float4s of
// the same row (independent loads, no register batch to collapse). Exact kill
// condition (real-math equivalent of the reference):
//   sigmoid(logit+noise) > 0.5  <=>  L2/L1 + eps < exp(logit) = r
//                               <=>  L2 > (r - eps)*L1   (L1 = log(u1+eps) < 0)
// ---------------------------------------------------------------------------
__device__ __forceinline__ void eval4(float4 v, float thr, float rm,
                                      int ubase, int row,
                                      const float* __restrict__ u1) {
    const float m = fmaxf(fmaxf(v.x, v.y), fmaxf(v.z, v.w));
    if (m > thr) {
        float vs[4] = {v.x, v.y, v.z, v.w};
#pragma unroll
        for (int k = 0; k < 4; ++k) {
            if (vs[k] > thr) {
                float L1 = __logf(u1[ubase + k] + EPSF);
                float L2 = __logf(vs[k] + EPSF);
                if (L2 > rm * L1) atomicMin(&g_tkill[(ubase + k) - row * BB], row);
            }
        }
    }
}

__global__ void __launch_bounds__(NTHR) kill_kernel(const float* __restrict__ u1,
                                                    const float* __restrict__ u2,
                                                    float* __restrict__ out) {
    const int tid  = threadIdx.x;
    const int lane = tid & 31;
    const int wg   = blockIdx.x * (NTHR / 32) + (tid >> 5);  // global warp id
    const int seg  = wg & 15;                                // 64-quad segment
    const int ta   = __ldg(&g_tactive);
    const float4* __restrict__ u2v = (const float4*)u2;

    const int q0 = seg * 64 + lane;        // first quad (coalesced across warp)
    for (int row = wg >> 4; row < ta; row += RPP) {
        const float2 rd = __ldg(&g_row[row]);       // uniform -> broadcast
        const int rb = row * (BB / 4);
        const float4 a = u2v[rb + q0];              // two independent loads,
        const float4 b = u2v[rb + q0 + 32];         // issued back-to-back
        eval4(a, rd.x, rd.y, row * BB + q0 * 4,        row, u1);
        eval4(b, rd.x, rd.y, row * BB + (q0 + 32) * 4, row, u1);
    }

    // ---- ticketed final reduction: last block gathers and means ----
    __shared__ bool s_last;
    __threadfence();
    if (tid == 0) s_last = (atomicAdd(&g_done, 1u) == NBLK - 1u);
    __syncthreads();
    if (!s_last) return;
    __threadfence();

    int kk[BB / NTHR];
#pragma unroll
    for (int it = 0; it < BB / NTHR; ++it) kk[it] = g_tkill[tid + it * NTHR];
    double s = 0.0;
#pragma unroll
    for (int it = 0; it < BB / NTHR; ++it) s += (double)g_pref[kk[it]];

    __shared__ double sh[NTHR];
    sh[tid] = s;
    __syncthreads();
#pragma unroll
    for (int off = NTHR / 2; off > 0; off >>= 1) {
        if (tid < off) sh[tid] += sh[tid + off];
        __syncthreads();
    }
    if (tid == 0) out[0] = (float)(sh[0] / (double)BB);
}

// ---------------------------------------------------------------------------
extern "C" void kernel_launch(void* const* d_in, const int* in_sizes, int n_in,
                              void* d_out, int out_size) {
    const float* acts = (const float*)d_in[0];
    const float* u1   = (const float*)d_in[1];
    const float* u2   = (const float*)d_in[2];

    scan_kernel<<<1, NTH>>>(acts);
    kill_kernel<<<NBLK, NTHR>>>(u1, u2, (float*)d_out);
}